// round 10
// baseline (speedup 1.0000x reference)
#include <cuda_runtime.h>

#define NF    20480
#define NACC  128
#define BATCH 4096
#define NTASK (2 * BATCH)    // (row, side) tasks
#define REC   132            // 128 acc weights + 2 psqt + 2 pad (528B, 16B aligned)
#define RECV4 33             // REC/4
#define QTR4  (NF / 4 / 4)   // 1280 float4 per quarter-row
#define ITERS (NF / 4 / 512) // 10 iterations of 512 floats per quarter
#define CAP   96             // per-warp active-feature list capacity
#define FULLM 0xffffffffu
#define GRID_MAIN (148 * 12) // persistent: exactly-resident at 12 blocks/SM

// Packed feature-major table: g_table[f*132 + s], s<128 -> acc_w[s][f],
// s==128/129 -> psqt_w[0/1][f], s==130/131 -> 0.
__device__ float g_table[(size_t)NF * REC];
__device__ int   g_ticket;           // dynamic task counter (reset per launch)

// ---------------------------------------------------------------------------
// Kernel 1: reset ticket + zero output + transpose acc_w/psqt_w into g_table.
// Reset/zero are ordered before the PDL trigger (threadfence), so the main
// kernel (which launches only after ALL builder blocks trigger) sees them.
// ---------------------------------------------------------------------------
__global__ __launch_bounds__(256) void build_table_kernel(
    const float* __restrict__ acc_w,
    const float* __restrict__ psqt_w,
    float* __restrict__ out)
{
    if (blockIdx.x == 0 && threadIdx.x == 0) g_ticket = 0;
    if (blockIdx.x < 32) out[blockIdx.x * 256 + threadIdx.x] = 0.0f;
    __threadfence();
    cudaTriggerProgrammaticLaunchCompletion();

    __shared__ float tile[32][133];
    const int f0 = blockIdx.x * 32;

    for (int idx = threadIdx.x; idx < 32 * REC; idx += 256) {
        int s  = idx >> 5;
        int fl = idx & 31;
        int f  = f0 + fl;
        float v = 0.0f;
        if (s < NACC)      v = acc_w[(size_t)s * NF + f];
        else if (s == 128) v = psqt_w[f];
        else if (s == 129) v = psqt_w[NF + f];
        tile[fl][s] = v;
    }
    __syncthreads();
    for (int idx = threadIdx.x; idx < 32 * REC; idx += 256) {
        int fl = idx / REC;
        int s  = idx - fl * REC;
        g_table[(size_t)(f0 + fl) * REC + s] = tile[fl][s];
    }
}

// ---------------------------------------------------------------------------
// Kernel 2: persistent blocks, dynamic ticket per (row, side) task.
// 128 threads = 4 warps, one feature-quarter each. One barrier per task:
// next ticket is prefetched before the publish-barrier (parity slot), and
// accumulator smem is parity double-buffered so warps 1-3 stream task k+1
// while warp 0 finishes task k's epilogue.
// ---------------------------------------------------------------------------
__global__ __launch_bounds__(128, 12) void nnue_main_kernel(
    const float* __restrict__ white,
    const float* __restrict__ black,
    const float* __restrict__ acc_b,
    const float* __restrict__ out_w,
    float* __restrict__ out)
{
    const int tid  = threadIdx.x;
    const int q    = tid >> 5;          // warp = feature quarter, 0..3
    const int lane = tid & 31;

    // NOTE: explicit 16B alignment — these are accessed via float4 casts.
    __shared__ __align__(16) float s_acc[2][4][NACC]; // parity x quarter partials
    __shared__ __align__(16) int   s_idx[4][CAP];     // per-warp active feature ids
    __shared__ __align__(16) float s_ps[2][4][2];     // parity x quarter psqt
    __shared__ int s_task[2];                         // parity-indexed task ids

    // hoisted task-invariant loads (harness inputs, not builder outputs)
    const float4 bias = reinterpret_cast<const float4*>(acc_b)[lane];
    const float4 ow0  = reinterpret_cast<const float4*>(out_w)[lane];
    const float4 ow1  = reinterpret_cast<const float4*>(out_w)[32 + lane];
    const float4* __restrict__ tbl = reinterpret_cast<const float4*>(g_table);
    const int fbase4 = q * QTR4;

    if (tid == 0) s_task[0] = atomicAdd(&g_ticket, 1);
    __syncthreads();

    bool synced = false;
    int k = 0;
    while (true) {
        const int p = k & 1;
        const int t = s_task[p];
        if (t >= NTASK) break;
        const int side = t & 1;
        const int row  = t >> 1;

        const float* base_ptr = (side == 0 ? white : black);
        const float4* __restrict__ rowp =
            reinterpret_cast<const float4*>(base_ptr + (size_t)row * NF) + q * QTR4;

        // ================= Phase 1: streaming scan =================
        int cnt = 0;                    // warp-uniform

        float4 q0 = __ldcs(rowp + lane);
        float4 q1 = __ldcs(rowp + lane + 32);
        float4 q2 = __ldcs(rowp + lane + 64);
        float4 q3 = __ldcs(rowp + lane + 96);

        #pragma unroll 1
        for (int it = 0; it < ITERS; ++it) {
            float4 n0, n1, n2, n3;
            if (it + 1 < ITERS) {
                const int b4 = (it + 1) * 128 + lane;
                n0 = __ldcs(rowp + b4);
                n1 = __ldcs(rowp + b4 + 32);
                n2 = __ldcs(rowp + b4 + 64);
                n3 = __ldcs(rowp + b4 + 96);
            }

            #pragma unroll
            for (int u = 0; u < 4; ++u) {
                float4 qq = (u == 0) ? q0 : (u == 1) ? q1 : (u == 2) ? q2 : q3;
                unsigned mask4 = (unsigned)(qq.x != 0.0f)
                               | ((unsigned)(qq.y != 0.0f) << 1)
                               | ((unsigned)(qq.z != 0.0f) << 2)
                               | ((unsigned)(qq.w != 0.0f) << 3);
                unsigned any_m = __ballot_sync(FULLM, mask4 != 0u);
                while (any_m) {                 // warp-uniform loop
                    int src = __ffs(any_m) - 1;
                    any_m &= any_m - 1;
                    unsigned m4 = __shfl_sync(FULLM, mask4, src);
                    int bj = 4 * (fbase4 + it * 128 + 32 * u + src);
                    while (m4) {
                        int c = __ffs(m4) - 1;
                        m4 &= m4 - 1;
                        if (lane == 0 && cnt < CAP) s_idx[q][cnt] = bj + c;
                        ++cnt;
                    }
                }
            }
            q0 = n0; q1 = n1; q2 = n2; q3 = n3;
        }
        if (cnt > CAP) cnt = CAP;
        __syncwarp();                    // make s_idx visible to whole warp

        if (!synced) { cudaGridDependencySynchronize(); synced = true; }

        // ================= Phase 2: batched gather =================
        float ax, ay, az, aw;
        if (q == 0) { ax = bias.x; ay = bias.y; az = bias.z; aw = bias.w; }
        else        { ax = ay = az = aw = 0.0f; }
        float p0 = 0.0f, p1 = 0.0f;      // psqt partials (lanes 0 and 1)

        int i = 0;
        #pragma unroll 1
        for (; i + 2 <= cnt; i += 2) {   // two independent L2 loads in flight
            int j0 = s_idx[q][i];
            int j1 = s_idx[q][i + 1];
            float4 t0 = tbl[(size_t)j0 * RECV4 + lane];
            float4 t1 = tbl[(size_t)j1 * RECV4 + lane];
            if (lane < 2) {
                int jp = (lane == 0) ? j0 : j1;
                float4 pq = tbl[(size_t)jp * RECV4 + 32];
                p0 += pq.x; p1 += pq.y;
            }
            ax += t0.x; ay += t0.y; az += t0.z; aw += t0.w;
            ax += t1.x; ay += t1.y; az += t1.z; aw += t1.w;
        }
        if (i < cnt) {
            int j0 = s_idx[q][i];
            float4 t0 = tbl[(size_t)j0 * RECV4 + lane];
            if (lane == 0) {
                float4 pq = tbl[(size_t)j0 * RECV4 + 32];
                p0 += pq.x; p1 += pq.y;
            }
            ax += t0.x; ay += t0.y; az += t0.z; aw += t0.w;
        }
        #pragma unroll
        for (int off = 16; off > 0; off >>= 1) {
            p0 += __shfl_xor_sync(FULLM, p0, off);
            p1 += __shfl_xor_sync(FULLM, p1, off);
        }

        // ---- prefetch next ticket + publish partials, single barrier ----
        if (tid == 0) s_task[p ^ 1] = atomicAdd(&g_ticket, 1);
        reinterpret_cast<float4*>(&s_acc[p][q][0])[lane] =
            make_float4(ax, ay, az, aw);
        if (lane == 0) { s_ps[p][q][0] = p0; s_ps[p][q][1] = p1; }
        __syncthreads();

        // ---- warp 0: reduce quarters, clip, output layer, signed atomic ----
        if (q == 0) {
            float4 a0 = reinterpret_cast<const float4*>(&s_acc[p][0][0])[lane];
            float4 a1 = reinterpret_cast<const float4*>(&s_acc[p][1][0])[lane];
            float4 a2 = reinterpret_cast<const float4*>(&s_acc[p][2][0])[lane];
            float4 a3 = reinterpret_cast<const float4*>(&s_acc[p][3][0])[lane];
            float rx = a0.x + a1.x + a2.x + a3.x;
            float ry = a0.y + a1.y + a2.y + a3.y;
            float rz = a0.z + a1.z + a2.z + a3.z;
            float rw = a0.w + a1.w + a2.w + a3.w;

            rx = fminf(fmaxf(rx, 0.0f), 1.0f);
            ry = fminf(fmaxf(ry, 0.0f), 1.0f);
            rz = fminf(fmaxf(rz, 0.0f), 1.0f);
            rw = fminf(fmaxf(rw, 0.0f), 1.0f);

            float s0 = rx * ow0.x + ry * ow0.y + rz * ow0.z + rw * ow0.w;
            float s1 = rx * ow1.x + ry * ow1.y + rz * ow1.z + rw * ow1.w;
            #pragma unroll
            for (int off = 16; off > 0; off >>= 1) {
                s0 += __shfl_xor_sync(FULLM, s0, off);
                s1 += __shfl_xor_sync(FULLM, s1, off);
            }
            if (lane == 0) {
                float pp0 = s_ps[p][0][0] + s_ps[p][1][0]
                          + s_ps[p][2][0] + s_ps[p][3][0];
                float pp1 = s_ps[p][0][1] + s_ps[p][1][1]
                          + s_ps[p][2][1] + s_ps[p][3][1];
                const float sgn = (side == 0) ? 1.0f : -1.0f;
                // exactly two adds per element (+white, -black): commutative
                // -> bitwise deterministic regardless of ticket order.
                atomicAdd(&out[row * 2 + 0], sgn * (pp0 + s0));
                atomicAdd(&out[row * 2 + 1], sgn * (pp1 + s1));
            }
        }
        ++k;
    }
}

// ---------------------------------------------------------------------------
extern "C" void kernel_launch(void* const* d_in, const int* in_sizes, int n_in,
                              void* d_out, int out_size)
{
    const float* white  = (const float*)d_in[0];
    const float* black  = (const float*)d_in[1];
    const float* psqt_w = (const float*)d_in[2];
    const float* acc_w  = (const float*)d_in[3];
    const float* acc_b  = (const float*)d_in[4];
    const float* out_w  = (const float*)d_in[5];
    (void)in_sizes; (void)n_in; (void)out_size;

    build_table_kernel<<<NF / 32, 256>>>(acc_w, psqt_w, (float*)d_out);

    // PDL: builder resets ticket/zeroes out, triggers at entry; persistent
    // main kernel co-schedules, streams its first tasks, and grid-syncs
    // before the first table gather.
    cudaLaunchConfig_t cfg = {};
    cfg.gridDim  = dim3(GRID_MAIN);
    cfg.blockDim = dim3(128);
    cfg.dynamicSmemBytes = 0;
    cfg.stream = 0;
    cudaLaunchAttribute attrs[1];
    attrs[0].id = cudaLaunchAttributeProgrammaticStreamSerialization;
    attrs[0].val.programmaticStreamSerializationAllowed = 1;
    cfg.attrs = attrs;
    cfg.numAttrs = 1;
    cudaLaunchKernelEx(&cfg, nnue_main_kernel,
                       white, black, acc_b, out_w, (float*)d_out);
}

// round 11
// speedup vs baseline: 1.0685x; 1.0685x over previous
#include <cuda_runtime.h>

#define NF    20480
#define NACC  128
#define BATCH 4096
#define REC   132            // 128 acc weights + 2 psqt + 2 pad (528B, 16B aligned)
#define RECV4 33             // REC/4
#define QTR4  (NF / 4 / 4)   // 1280 float4 per quarter-row
#define ITERS (NF / 4 / 512) // 10 iterations of 512 floats per quarter
#define CAP   96             // per-warp active-feature list capacity
#define FULLM 0xffffffffu

// Packed feature-major table: g_table[f*132 + s], s<128 -> acc_w[s][f],
// s==128/129 -> psqt_w[0/1][f], s==130/131 -> 0.
__device__ float g_table[(size_t)NF * REC];

// ---------------------------------------------------------------------------
// Kernel 1: zero output + transpose acc_w/psqt_w into g_table.
// Zero is ordered before the PDL trigger (threadfence), so the main kernel
// (launched only after ALL builder blocks trigger) sees it.
// ---------------------------------------------------------------------------
__global__ __launch_bounds__(256) void build_table_kernel(
    const float* __restrict__ acc_w,
    const float* __restrict__ psqt_w,
    float* __restrict__ out)
{
    if (blockIdx.x < 32) out[blockIdx.x * 256 + threadIdx.x] = 0.0f;
    __threadfence();
    cudaTriggerProgrammaticLaunchCompletion();

    __shared__ float tile[32][133];
    const int f0 = blockIdx.x * 32;

    for (int idx = threadIdx.x; idx < 32 * REC; idx += 256) {
        int s  = idx >> 5;
        int fl = idx & 31;
        int f  = f0 + fl;
        float v = 0.0f;
        if (s < NACC)      v = acc_w[(size_t)s * NF + f];
        else if (s == 128) v = psqt_w[f];
        else if (s == 129) v = psqt_w[NF + f];
        tile[fl][s] = v;
    }
    __syncthreads();
    for (int idx = threadIdx.x; idx < 32 * REC; idx += 256) {
        int fl = idx / REC;
        int s  = idx - fl * REC;
        g_table[(size_t)(f0 + fl) * REC + s] = tile[fl][s];
    }
}

// ---------------------------------------------------------------------------
// Kernel 2: block = (row, side) [static, CLC-scheduled], 128 threads = 4 warps,
// one feature-quarter per warp.
// Phase 1: pure streaming scan (integer nonzero tests, lazy mask) -> index list.
// Grid sync (builder overlapped via PDL trigger).
// Phase 2: MLP-4 batched L2 gather, quarter merge, clip + output layer,
//          atomicAdd(+/-) into out[row] (exactly 2 adds/element: deterministic).
// ---------------------------------------------------------------------------
__global__ __launch_bounds__(128, 10) void nnue_main_kernel(
    const float* __restrict__ white,
    const float* __restrict__ black,
    const float* __restrict__ acc_b,
    const float* __restrict__ out_w,
    float* __restrict__ out)
{
    const int tid  = threadIdx.x;
    const int q    = tid >> 5;          // warp = feature quarter, 0..3
    const int lane = tid & 31;
    const int side = blockIdx.x & 1;    // 0=white, 1=black
    const int row  = blockIdx.x >> 1;

    // explicit 16B alignment — accessed via float4 casts (R9 lesson)
    __shared__ __align__(16) float s_acc[4][NACC]; // per-quarter partials
    __shared__ __align__(16) int   s_idx[4][CAP];  // per-warp active features
    __shared__ __align__(16) float s_ps[4][2];     // per-quarter psqt partials

    const float* base_ptr = (side == 0 ? white : black);
    const uint4* __restrict__ rowp =
        reinterpret_cast<const uint4*>(base_ptr + (size_t)row * NF) + q * QTR4;
    const int fbase4 = q * QTR4;

    // ================= Phase 1: streaming scan =================
    int cnt = 0;                        // warp-uniform

    uint4 q0 = __ldcs(rowp + lane);
    uint4 q1 = __ldcs(rowp + lane + 32);
    uint4 q2 = __ldcs(rowp + lane + 64);
    uint4 q3 = __ldcs(rowp + lane + 96);

    #pragma unroll 1
    for (int it = 0; it < ITERS; ++it) {
        uint4 n0, n1, n2, n3;
        if (it + 1 < ITERS) {
            const int b4 = (it + 1) * 128 + lane;
            n0 = __ldcs(rowp + b4);
            n1 = __ldcs(rowp + b4 + 32);
            n2 = __ldcs(rowp + b4 + 64);
            n3 = __ldcs(rowp + b4 + 96);
        }

        #pragma unroll
        for (int u = 0; u < 4; ++u) {
            uint4 qq = (u == 0) ? q0 : (u == 1) ? q1 : (u == 2) ? q2 : q3;
            // inputs are exactly 0.0f or 1.0f -> integer nonzero test is exact
            unsigned orw = qq.x | qq.y | qq.z | qq.w;
            unsigned any_m = __ballot_sync(FULLM, orw != 0u);
            if (any_m) {                        // warp-uniform rare path (~19%)
                unsigned mask4 = (unsigned)(qq.x != 0u)
                               | ((unsigned)(qq.y != 0u) << 1)
                               | ((unsigned)(qq.z != 0u) << 2)
                               | ((unsigned)(qq.w != 0u) << 3);
                do {
                    int src = __ffs(any_m) - 1;
                    any_m &= any_m - 1;
                    unsigned m4 = __shfl_sync(FULLM, mask4, src);
                    int bj = 4 * (fbase4 + it * 128 + 32 * u + src);
                    while (m4) {
                        int c = __ffs(m4) - 1;
                        m4 &= m4 - 1;
                        if (lane == 0 && cnt < CAP) s_idx[q][cnt] = bj + c;
                        ++cnt;
                    }
                } while (any_m);
            }
        }
        q0 = n0; q1 = n1; q2 = n2; q3 = n3;
    }
    if (cnt > CAP) cnt = CAP;
    __syncwarp();                        // make s_idx visible to whole warp

    // builder finished long ago (PDL overlap); returns immediately
    cudaGridDependencySynchronize();

    // ================= Phase 2: batched gather, MLP=4 =================
    const float4* __restrict__ tbl = reinterpret_cast<const float4*>(g_table);

    float ax, ay, az, aw;
    if (q == 0) {
        float4 b = reinterpret_cast<const float4*>(acc_b)[lane];
        ax = b.x; ay = b.y; az = b.z; aw = b.w;
    } else {
        ax = ay = az = aw = 0.0f;
    }
    float p0 = 0.0f, p1 = 0.0f;          // psqt partials (lanes 0..3)

    int i = 0;
    #pragma unroll 1
    for (; i + 4 <= cnt; i += 4) {       // four independent L2 loads in flight
        int j0 = s_idx[q][i];
        int j1 = s_idx[q][i + 1];
        int j2 = s_idx[q][i + 2];
        int j3 = s_idx[q][i + 3];
        float4 t0 = tbl[(size_t)j0 * RECV4 + lane];
        float4 t1 = tbl[(size_t)j1 * RECV4 + lane];
        float4 t2 = tbl[(size_t)j2 * RECV4 + lane];
        float4 t3 = tbl[(size_t)j3 * RECV4 + lane];
        if (lane < 4) {                  // lane L handles psqt of j(i+L)
            int jp = s_idx[q][i + lane];
            float4 pq = tbl[(size_t)jp * RECV4 + 32];
            p0 += pq.x; p1 += pq.y;
        }
        ax += t0.x; ay += t0.y; az += t0.z; aw += t0.w;
        ax += t1.x; ay += t1.y; az += t1.z; aw += t1.w;
        ax += t2.x; ay += t2.y; az += t2.z; aw += t2.w;
        ax += t3.x; ay += t3.y; az += t3.z; aw += t3.w;
    }
    #pragma unroll 1
    for (; i < cnt; ++i) {               // remainder (0..3)
        int j0 = s_idx[q][i];
        float4 t0 = tbl[(size_t)j0 * RECV4 + lane];
        if (lane == 0) {
            float4 pq = tbl[(size_t)j0 * RECV4 + 32];
            p0 += pq.x; p1 += pq.y;
        }
        ax += t0.x; ay += t0.y; az += t0.z; aw += t0.w;
    }
    // reduce psqt partials (live in lanes 0..3) across the warp
    #pragma unroll
    for (int off = 16; off > 0; off >>= 1) {
        p0 += __shfl_xor_sync(FULLM, p0, off);
        p1 += __shfl_xor_sync(FULLM, p1, off);
    }

    // ---- publish partial accumulators (merge BEFORE clip) ----
    reinterpret_cast<float4*>(&s_acc[q][0])[lane] = make_float4(ax, ay, az, aw);
    if (lane == 0) { s_ps[q][0] = p0; s_ps[q][1] = p1; }
    __syncthreads();

    // ---- warp 0: reduce quarters, clip, output layer, signed atomic ----
    if (q == 0) {
        float4 a0 = reinterpret_cast<const float4*>(&s_acc[0][0])[lane];
        float4 a1 = reinterpret_cast<const float4*>(&s_acc[1][0])[lane];
        float4 a2 = reinterpret_cast<const float4*>(&s_acc[2][0])[lane];
        float4 a3 = reinterpret_cast<const float4*>(&s_acc[3][0])[lane];
        float rx = a0.x + a1.x + a2.x + a3.x;
        float ry = a0.y + a1.y + a2.y + a3.y;
        float rz = a0.z + a1.z + a2.z + a3.z;
        float rw = a0.w + a1.w + a2.w + a3.w;

        rx = fminf(fmaxf(rx, 0.0f), 1.0f);
        ry = fminf(fmaxf(ry, 0.0f), 1.0f);
        rz = fminf(fmaxf(rz, 0.0f), 1.0f);
        rw = fminf(fmaxf(rw, 0.0f), 1.0f);

        const float4 ow0 = reinterpret_cast<const float4*>(out_w)[lane];
        const float4 ow1 = reinterpret_cast<const float4*>(out_w)[32 + lane];
        float s0 = rx * ow0.x + ry * ow0.y + rz * ow0.z + rw * ow0.w;
        float s1 = rx * ow1.x + ry * ow1.y + rz * ow1.z + rw * ow1.w;
        #pragma unroll
        for (int off = 16; off > 0; off >>= 1) {
            s0 += __shfl_xor_sync(FULLM, s0, off);
            s1 += __shfl_xor_sync(FULLM, s1, off);
        }
        if (lane == 0) {
            float pp0 = s_ps[0][0] + s_ps[1][0] + s_ps[2][0] + s_ps[3][0];
            float pp1 = s_ps[0][1] + s_ps[1][1] + s_ps[2][1] + s_ps[3][1];
            const float sgn = (side == 0) ? 1.0f : -1.0f;
            // exactly two adds per element (+white, -black): commutative
            // -> bitwise deterministic regardless of scheduling order.
            atomicAdd(&out[row * 2 + 0], sgn * (pp0 + s0));
            atomicAdd(&out[row * 2 + 1], sgn * (pp1 + s1));
        }
    }
}

// ---------------------------------------------------------------------------
extern "C" void kernel_launch(void* const* d_in, const int* in_sizes, int n_in,
                              void* d_out, int out_size)
{
    const float* white  = (const float*)d_in[0];
    const float* black  = (const float*)d_in[1];
    const float* psqt_w = (const float*)d_in[2];
    const float* acc_w  = (const float*)d_in[3];
    const float* acc_b  = (const float*)d_in[4];
    const float* out_w  = (const float*)d_in[5];
    (void)in_sizes; (void)n_in; (void)out_size;

    build_table_kernel<<<NF / 32, 256>>>(acc_w, psqt_w, (float*)d_out);

    // PDL: builder zeroes out + triggers at entry; main kernel co-schedules,
    // streams inputs during the builder, grid-syncs before first table gather.
    cudaLaunchConfig_t cfg = {};
    cfg.gridDim  = dim3(BATCH * 2);
    cfg.blockDim = dim3(128);
    cfg.dynamicSmemBytes = 0;
    cfg.stream = 0;
    cudaLaunchAttribute attrs[1];
    attrs[0].id = cudaLaunchAttributeProgrammaticStreamSerialization;
    attrs[0].val.programmaticStreamSerializationAllowed = 1;
    cfg.attrs = attrs;
    cfg.numAttrs = 1;
    cudaLaunchKernelEx(&cfg, nnue_main_kernel,
                       white, black, acc_b, out_w, (float*)d_out);
}